// round 16
// baseline (speedup 1.0000x reference)
#include <cuda_runtime.h>
#include <cuda_fp16.h>
#include <cstdint>

// WaveletWindowAttention fused kernel (R15): 512 threads/CTA, 512 CTAs,
// 2 CTAs/SM. vs R14: SMEM diet — ll/lh/hh subbands live in L2-resident
// __device__ scratch; 4 batches of 2 heads (P halved); q-conv for batch b+1
// pipelined on warps 8-15; hlT stride 268 (conflict-free B1b B-frags);
// SCALE folded into q; PV A-fragments loaded once per head.

#define NTH 512
#define PSTR 72           // P row stride in halves
#define PHEAD 4608        // 64*72 halves per head
#define VSTR 72           // V16 row stride in halves
#define QS2 70            // Q [n][cl64] row stride in halves
#define QBUF 4480         // halves per Q buffer (64*70)
#define HTS 268           // hlT [m][c] row stride in halves
#define SCQ 0.17677669529663687f

__device__ __half g_WpH[65536];   // proj weights fp16 in HMMA A-fragment order
__device__ float  g_BiasC[32768]; // bias in HMMA C-fragment order (raw)
__device__ __half g_llS[512 * 16384];
__device__ __half g_lhS[512 * 16384];
__device__ __half g_hhS[512 * 16384];

// fused prep: write-coalesced gather for both tables
__global__ void prep_all(const float* __restrict__ pjw,
                         const float* __restrict__ atb,
                         const int* __restrict__ bix) {
    int tid = blockIdx.x * 256 + threadIdx.x;   // 73728 threads
    if (tid < 65536) {
        int j = tid;
        int aidx = j & 7, lane = (j >> 3) & 31, ks = (j >> 8) & 15, mt = j >> 12;
        int m = (lane >> 2) | (((aidx >> 1) & 1) << 3);
        int k = ((lane & 3) << 1) | (aidx & 1) | ((aidx >> 2) << 3);
        g_WpH[j] = __float2half(pjw[(((mt << 4) + m) << 8) + (ks << 4) + k]);
    } else {
        int u = tid - 65536;   // 0..8191 -> float4 of g_BiasC
        int h = u >> 10, mt = (u >> 8) & 3, nt = (u >> 5) & 7, lane = u & 31;
        int g = lane >> 2, t = lane & 3;
        int n0 = mt * 16 + g, m0 = nt * 8 + t * 2;
        float4 v;
        v.x = atb[(h << 6) + bix[(n0 << 6) + m0]];
        v.y = atb[(h << 6) + bix[(n0 << 6) + m0 + 1]];
        v.z = atb[(h << 6) + bix[((n0 + 8) << 6) + m0]];
        v.w = atb[(h << 6) + bix[((n0 + 8) << 6) + m0 + 1]];
        ((float4*)g_BiasC)[u] = v;
    }
}

__device__ __forceinline__ void hmma16816(float* c4, const uint32_t* a4,
                                          uint32_t b0, uint32_t b1) {
    asm volatile(
        "mma.sync.aligned.m16n8k16.row.col.f32.f16.f16.f32 "
        "{%0,%1,%2,%3}, {%4,%5,%6,%7}, {%8,%9}, {%0,%1,%2,%3};"
        : "+f"(c4[0]), "+f"(c4[1]), "+f"(c4[2]), "+f"(c4[3])
        : "r"(a4[0]), "r"(a4[1]), "r"(a4[2]), "r"(a4[3]), "r"(b0), "r"(b1));
}

__device__ __forceinline__ void barn(int id, int cnt) {
    asm volatile("bar.sync %0, %1;" :: "r"(id), "r"(cnt) : "memory");
}

// q-conv for one strip: channel ch, output pair (n, n+1) from spatial slot s
__device__ __forceinline__ void qconv_strip(const __half* lhw,
                                            const float* dww, const float* dwb,
                                            __half* Qb, int ch, int cl64, int s) {
    int py = s >> 2;
    int px0 = (s & 3) << 1;
    int base = px0 >> 1;
    const float* wd = dww + ch * 25;
    float a0 = __ldg(dwb + ch), a1 = a0;
    const __half2* row = (const __half2*)(lhw + (ch << 6));
    #pragma unroll
    for (int uu = 0; uu < 5; uu++) {
        int yy = py + uu - 2;
        if ((unsigned)yy < 8u) {
            const __half2* r = row + (yy << 2);
            const float* w = wd + uu * 5;
            if (base >= 1) {
                float2 h = __half22float2(r[base - 1]);
                a0 += h.x * w[0] + h.y * w[1];
                a1 += h.y * w[0];
            }
            {
                float2 h = __half22float2(r[base]);
                a0 += h.x * w[2] + h.y * w[3];
                a1 += h.x * w[1] + h.y * w[2];
            }
            if (base <= 2) {
                float2 h = __half22float2(r[base + 1]);
                a0 += h.x * w[4];
                a1 += h.x * w[3] + h.y * w[4];
            }
        }
    }
    int n = (py << 3) + px0;
    Qb[n * QS2 + cl64]       = __float2half(a0 * SCQ);
    Qb[(n + 1) * QS2 + cl64] = __float2half(a1 * SCQ);
}

// ---- per-CTA shared memory layout (bytes), total 113664 ----
// @0      hlT  f16 [64][268] (34304)          [A -> B1b, D]
// @34304  actT f16 [64][264] (33792)          [B2 -> C] | PO_B f32[256][32] (D)
// @68096  P f16 [2][64][72] (18432)           [B1b->B2] | S_wt(A) | PO_A part
// @86528  Q f16 2x[64][70] (17920)            [B1a->B1b] | PO_A part
//         (PO_A f32[256][32] = 32768 spans 68096..100864)
// @104448 V16A (4608), @109056 V16B (4608) -> end 113664
#define SMEM_BYTES 113664

__global__ void __launch_bounds__(NTH, 2)
wwa_kernel(const float* __restrict__ x,   const float* __restrict__ wtf,
           const float* __restrict__ iwtf,const float* __restrict__ dww,
           const float* __restrict__ dwb, const float* __restrict__ pjb,
           float* __restrict__ out)
{
    extern __shared__ unsigned char sm[];
    __half* hlT  = (__half*)sm;
    __half* actT = (__half*)(sm + 34304);
    float*  PO_B = (float*)(sm + 34304);
    __half* P    = (__half*)(sm + 68096);
    float*  S_wt = (float*)(sm + 68096);
    float*  PO_A = (float*)(sm + 68096);
    __half* Q    = (__half*)(sm + 86528);
    __half* V16A = (__half*)(sm + 104448);
    __half* V16B = (__half*)(sm + 109056);

    const int tid  = threadIdx.x;
    const int wid  = tid >> 5;
    const int lane = tid & 31;
    const int widx = blockIdx.x;
    const int wb = widx >> 8;
    const int wy = (widx >> 4) & 15;
    const int wx = widx & 15;
    const int g  = lane >> 2;
    const int t  = lane & 3;

    __half* llw = g_llS + (size_t)widx * 16384;
    __half* lhw = g_lhS + (size_t)widx * 16384;
    __half* hhw = g_hhS + (size_t)widx * 16384;

    for (int i = tid; i < 4096; i += NTH) S_wt[i] = wtf[i];
    __syncthreads();

    // ================= Phase A: forward wavelet =================
    {
        const float* xb = x + (size_t)wb * (256u * 256u * 256u);
        #pragma unroll 4
        for (int rep = 0; rep < 16; rep++) {
            int u = tid + rep * NTH;        // (c, i, k)
            int c = u >> 5;
            int i = (u >> 2) & 7;
            int k = u & 3;
            int gy = (wy << 4) + (i << 1);
            int gx = (wx << 4) + (k << 2);
            const float* p = xb + (((c << 8) + gy) << 8) + gx;
            float4 a = *(const float4*)p;
            float4 b = *(const float4*)(p + 256);
            const float* w = S_wt + (c << 4);
            int pix = (i << 3) + (k << 1);
            int o0 = (c << 6) + pix;
            float v0, v1;
            v0 = a.x*w[0] + a.y*w[1] + b.x*w[2] + b.y*w[3];
            v1 = a.z*w[0] + a.w*w[1] + b.z*w[2] + b.w*w[3];
            *(__half2*)(llw + o0) = __floats2half2_rn(v0, v1);
            v0 = a.x*w[4] + a.y*w[5] + b.x*w[6] + b.y*w[7];
            v1 = a.z*w[4] + a.w*w[5] + b.z*w[6] + b.w*w[7];
            *(__half2*)(lhw + o0) = __floats2half2_rn(v0, v1);
            v0 = a.x*w[8] + a.y*w[9] + b.x*w[10] + b.y*w[11];
            v1 = a.z*w[8] + a.w*w[9] + b.z*w[10] + b.w*w[11];
            hlT[pix * HTS + c]       = __float2half(v0);
            hlT[(pix + 1) * HTS + c] = __float2half(v1);
            v0 = a.x*w[12] + a.y*w[13] + b.x*w[14] + b.y*w[15];
            v1 = a.z*w[12] + a.w*w[13] + b.z*w[14] + b.w*w[15];
            *(__half2*)(hhw + o0) = __floats2half2_rn(v0, v1);
        }
    }
    __syncthreads();

    // ---- V16A init (ll rows 0..31) + q-conv batch 0 (all warps) ----
    {
        int d  = tid >> 4;
        int m2 = (tid & 15) << 2;
        *(uint2*)(V16A + d * VSTR + m2) = *(const uint2*)(llw + (d << 6) + m2);
    }
    #pragma unroll
    for (int rep = 0; rep < 4; rep++) {
        int e = tid + rep * NTH;       // 2048 strips
        int cl64 = e >> 5;
        qconv_strip(lhw, dww, dwb, Q, cl64, cl64, e & 31);
    }
    __syncthreads();

    // ============ Phase B: 4 batches of 2 heads, pipelined ============
    for (int b = 0; b < 4; b++) {
        __half* Qb = Q + (b & 1) * QBUF;
        if (wid < 8) {
            // ---- B1b: QK^T via HMMA, bias C-init, reg softmax -> P ----
            const int hl = wid >> 2;       // head-in-batch (0/1)
            const int mt = wid & 3;
            const int hd1 = (b << 1) + hl;
            float fv0[16], fv1[16];
            {
                const float4* bc = (const float4*)g_BiasC
                    + (((hd1 << 2) + mt) << 8) + lane;
                #pragma unroll
                for (int nt = 0; nt < 8; nt++) {
                    float4 b4 = bc[nt << 5];
                    fv0[nt*2] = b4.x; fv0[nt*2+1] = b4.y;
                    fv1[nt*2] = b4.z; fv1[nt*2+1] = b4.w;
                }
            }
            const __half* qb = Qb + (mt * 16 + g) * QS2 + (hl << 5) + (t << 1);
            uint32_t A0[4], A1[4];
            A0[0] = *(const uint32_t*)(qb);
            A0[1] = *(const uint32_t*)(qb + 8 * QS2);
            A0[2] = *(const uint32_t*)(qb + 8);
            A0[3] = *(const uint32_t*)(qb + 8 * QS2 + 8);
            A1[0] = *(const uint32_t*)(qb + 16);
            A1[1] = *(const uint32_t*)(qb + 8 * QS2 + 16);
            A1[2] = *(const uint32_t*)(qb + 24);
            A1[3] = *(const uint32_t*)(qb + 8 * QS2 + 24);
            const __half* bt = hlT + (hd1 << 5) + (t << 1);
            #pragma unroll
            for (int nt = 0; nt < 8; nt++) {
                float c[4] = {fv0[nt*2], fv0[nt*2+1], fv1[nt*2], fv1[nt*2+1]};
                const __half* bp = bt + ((nt << 3) + g) * HTS;
                uint32_t b0 = *(const uint32_t*)(bp);
                uint32_t b1 = *(const uint32_t*)(bp + 8);
                hmma16816(c, A0, b0, b1);
                b0 = *(const uint32_t*)(bp + 16);
                b1 = *(const uint32_t*)(bp + 24);
                hmma16816(c, A1, b0, b1);
                fv0[nt*2] = c[0]; fv0[nt*2+1] = c[1];
                fv1[nt*2] = c[2]; fv1[nt*2+1] = c[3];
            }
            #pragma unroll
            for (int r = 0; r < 2; r++) {
                float* fv = r ? fv1 : fv0;
                int n = mt * 16 + g + (r << 3);
                float mx = fv[0];
                #pragma unroll
                for (int j = 1; j < 16; j++) mx = fmaxf(mx, fv[j]);
                mx = fmaxf(mx, __shfl_xor_sync(0xffffffffu, mx, 1));
                mx = fmaxf(mx, __shfl_xor_sync(0xffffffffu, mx, 2));
                float sum = 0.f;
                #pragma unroll
                for (int j = 0; j < 16; j++) { fv[j] = __expf(fv[j] - mx); sum += fv[j]; }
                sum += __shfl_xor_sync(0xffffffffu, sum, 1);
                sum += __shfl_xor_sync(0xffffffffu, sum, 2);
                float inv = 1.f / sum;
                __half* pr = P + hl * PHEAD + n * PSTR + (t << 1);
                #pragma unroll
                for (int nt = 0; nt < 8; nt++)
                    *(__half2*)(pr + (nt << 3)) =
                        __floats2half2_rn(fv[nt*2] * inv, fv[nt*2+1] * inv);
            }
            barn(3, 256);                  // P ready among warps 0-7

            // ---- B2: 2 chained heads, PV via HMMA ----
            const int mt2 = wid >> 2;      // 0/1
            const int ntp = wid & 3;       // nt pair
            for (int hl2 = 0; hl2 < 2; hl2++) {
                const int hd  = (b << 1) + hl2;
                const int ch0 = hd << 5;
                __half* Vcur = (hd & 1) ? V16B : V16A;
                __half* Vnxt = (hd & 1) ? V16A : V16B;
                const int d0 = mt2 * 16 + g;
                uint32_t lfa[2], lfb[2];
                if (hd < 7) {
                    #pragma unroll
                    for (int ntt = 0; ntt < 2; ntt++) {
                        int n0 = (((ntp << 1) + ntt) << 3) + (t << 1);
                        lfa[ntt] = *(const uint32_t*)(llw + ((ch0 + 32 + d0) << 6) + n0);
                        lfb[ntt] = *(const uint32_t*)(llw + ((ch0 + 40 + d0) << 6) + n0);
                    }
                }
                uint32_t A[4][4];
                {
                    const __half* ab2 = Vcur + d0 * VSTR + (t << 1);
                    #pragma unroll
                    for (int ks = 0; ks < 4; ks++) {
                        A[ks][0] = *(const uint32_t*)(ab2 + (ks << 4));
                        A[ks][1] = *(const uint32_t*)(ab2 + 8 * VSTR + (ks << 4));
                        A[ks][2] = *(const uint32_t*)(ab2 + (ks << 4) + 8);
                        A[ks][3] = *(const uint32_t*)(ab2 + 8 * VSTR + (ks << 4) + 8);
                    }
                }
                #pragma unroll
                for (int ntt = 0; ntt < 2; ntt++) {
                    int nt = (ntp << 1) + ntt;
                    int n0 = (nt << 3) + (t << 1);
                    float c[4] = {0.f, 0.f, 0.f, 0.f};
                    const __half* bb2 = P + hl2 * PHEAD + ((nt << 3) + g) * PSTR + (t << 1);
                    #pragma unroll
                    for (int ks = 0; ks < 4; ks++) {
                        uint32_t b0 = *(const uint32_t*)(bb2 + (ks << 4));
                        uint32_t b1 = *(const uint32_t*)(bb2 + (ks << 4) + 8);
                        hmma16816(c, A[ks], b0, b1);
                    }
                    actT[n0 * 264 + ch0 + d0]           = __float2half(fmaxf(c[0], 0.f));
                    actT[(n0 + 1) * 264 + ch0 + d0]     = __float2half(fmaxf(c[1], 0.f));
                    actT[n0 * 264 + ch0 + d0 + 8]       = __float2half(fmaxf(c[2], 0.f));
                    actT[(n0 + 1) * 264 + ch0 + d0 + 8] = __float2half(fmaxf(c[3], 0.f));
                    if (hd < 7) {
                        float2 f0 = __half22float2(*(__half2*)&lfa[ntt]);
                        float2 f1 = __half22float2(*(__half2*)&lfb[ntt]);
                        *(__half2*)(Vnxt + d0 * VSTR + n0)       = __floats2half2_rn(c[0] + f0.x, c[1] + f0.y);
                        *(__half2*)(Vnxt + (d0 + 8) * VSTR + n0) = __floats2half2_rn(c[2] + f1.x, c[3] + f1.y);
                    }
                }
                barn(3, 256);              // Vnxt visible
            }
        } else if (b < 3) {
            // ---- q-conv for batch b+1 (warps 8-15) ----
            __half* Qn = Q + ((b + 1) & 1) * QBUF;
            #pragma unroll
            for (int rep = 0; rep < 8; rep++) {
                int e = (tid - 256) + rep * 256;   // 2048 strips
                int cl64 = e >> 5;
                qconv_strip(lhw, dww, dwb, Qn, ((b + 1) << 6) + cl64, cl64, e & 31);
            }
        }
        __syncthreads();
    }

    // ===== Phase C: HMMA projection, sequential n-halves =====
    #pragma unroll 1
    for (int nh = 0; nh < 2; nh++) {
        float acc[4][4];
        #pragma unroll
        for (int i = 0; i < 4; i++)
            #pragma unroll
            for (int j = 0; j < 4; j++) acc[i][j] = 0.f;
        const uint4* afrag = (const uint4*)g_WpH + (wid << 9) + lane;
        const __half* bbase = actT + ((nh << 5) + g) * 264 + (t << 1);
        #pragma unroll 4
        for (int ks = 0; ks < 16; ks++) {
            uint4 a = afrag[ks << 5];
            const __half* bp = bbase + (ks << 4);
            #pragma unroll
            for (int ntl = 0; ntl < 4; ntl++) {
                uint32_t b0 = *(const uint32_t*)(bp + ntl * 8 * 264);
                uint32_t b1 = *(const uint32_t*)(bp + ntl * 8 * 264 + 8);
                hmma16816(acc[ntl], (const uint32_t*)&a, b0, b1);
            }
        }
        if (nh == 1) __syncthreads();   // all actT reads done before PO_B stores
        int o0 = (wid << 4) + g;
        float pb0 = pjb[o0], pb1 = pjb[o0 + 8];
        float* dst = (nh == 0) ? PO_A : PO_B;
        #pragma unroll
        for (int ntl = 0; ntl < 4; ntl++) {
            int nc = (t << 1) + (ntl << 3);
            *(float2*)(dst + (o0 << 5) + nc) =
                make_float2(acc[ntl][0] + pb0, acc[ntl][1] + pb0);
            *(float2*)(dst + ((o0 + 8) << 5) + nc) =
                make_float2(acc[ntl][2] + pb1, acc[ntl][3] + pb1);
        }
    }
    __syncthreads();

    // ================= Phase D: inverse wavelet -> out =================
    {
        float* ob = out + (size_t)wb * (256u * 256u * 256u);
        #pragma unroll 4
        for (int rep = 0; rep < 16; rep++) {
            int u = tid + rep * NTH;
            int c = u >> 5;
            int i = (u >> 2) & 7;
            int k = u & 3;
            int pix = (i << 3) + (k << 1);
            int o0 = (c << 6) + pix;
            const float4* iw4 = (const float4*)(iwtf + (c << 4));
            float4 w0 = __ldg(iw4), w1 = __ldg(iw4 + 1);
            float4 w2 = __ldg(iw4 + 2), w3 = __ldg(iw4 + 3);
            float2 llv = (pix < 32)
                ? *(const float2*)(PO_A + (c << 5) + pix)
                : *(const float2*)(PO_B + (c << 5) + pix - 32);
            float2 lh = __half22float2(*(const __half2*)(lhw + o0));
            float2 hl;
            hl.x = __half2float(hlT[pix * HTS + c]);
            hl.y = __half2float(hlT[(pix + 1) * HTS + c]);
            float2 hh = __half22float2(*(const __half2*)(hhw + o0));
            float4 r0, r1;
            r0.x = llv.x*w0.x + lh.x*w1.x + hl.x*w2.x + hh.x*w3.x;
            r0.y = llv.x*w0.y + lh.x*w1.y + hl.x*w2.y + hh.x*w3.y;
            r0.z = llv.y*w0.x + lh.y*w1.x + hl.y*w2.x + hh.y*w3.x;
            r0.w = llv.y*w0.y + lh.y*w1.y + hl.y*w2.y + hh.y*w3.y;
            r1.x = llv.x*w0.z + lh.x*w1.z + hl.x*w2.z + hh.x*w3.z;
            r1.y = llv.x*w0.w + lh.x*w1.w + hl.x*w2.w + hh.x*w3.w;
            r1.z = llv.y*w0.z + lh.y*w1.z + hl.y*w2.z + hh.y*w3.z;
            r1.w = llv.y*w0.w + lh.y*w1.w + hl.y*w2.w + hh.y*w3.w;
            int gy = (wy << 4) + (i << 1);
            int gx = (wx << 4) + (k << 2);
            float* q_ = ob + (((c << 8) + gy) << 8) + gx;
            *(float4*)q_ = r0;
            *(float4*)(q_ + 256) = r1;
        }
    }
}

extern "C" void kernel_launch(void* const* d_in, const int* in_sizes, int n_in,
                              void* d_out, int out_size) {
    const float* x    = (const float*)d_in[0];
    const float* wtf  = (const float*)d_in[1];
    const float* iwtf = (const float*)d_in[2];
    const float* dww  = (const float*)d_in[3];
    const float* dwb  = (const float*)d_in[4];
    const float* pjw  = (const float*)d_in[5];
    const float* pjb  = (const float*)d_in[6];
    const float* atb  = (const float*)d_in[7];
    const int*   bix  = (const int*)d_in[8];
    float* o = (float*)d_out;
    (void)in_sizes; (void)n_in; (void)out_size;
    prep_all<<<288, 256>>>(pjw, atb, bix);
    cudaFuncSetAttribute(wwa_kernel, cudaFuncAttributeMaxDynamicSharedMemorySize, SMEM_BYTES);
    wwa_kernel<<<512, NTH, SMEM_BYTES>>>(x, wtf, iwtf, dww, dwb, pjb, o);
}

// round 17
// speedup vs baseline: 1.0733x; 1.0733x over previous
#include <cuda_runtime.h>
#include <cuda_fp16.h>
#include <cstdint>

// WaveletWindowAttention fused kernel (R16 = R14 + two micro-opts).
// 1024 threads/CTA, 512 CTAs. R15's 2-CTA/SM restructure regressed (CTA
// phase-misalignment + L2 scratch latency) and is reverted.
// vs R14: SCALE folded into q at q-conv store (raw bias in g_BiasC, softmax
// scale loop deleted); hlT stride 258 -> 266 (B1b B-frag conflicts ~4->2 way).

#define NTH 1024
#define PSTR 72           // P row stride in halves
#define PHEAD 4608        // 64*72 halves per head
#define VSTR 72           // V16 row stride in halves
#define QS 134            // Q [n][cl] row stride in halves
#define HTS 266           // hlT [m][c] row stride in halves
#define SCQ 0.17677669529663687f

__device__ __half g_WpH[65536];   // proj weights fp16 in HMMA A-fragment order
__device__ float  g_BiasC[32768]; // raw bias in HMMA C-fragment order

// fused prep: write-coalesced gather for both tables
__global__ void prep_all(const float* __restrict__ pjw,
                         const float* __restrict__ atb,
                         const int* __restrict__ bix) {
    int tid = blockIdx.x * 256 + threadIdx.x;   // 73728 threads
    if (tid < 65536) {
        // g_WpH[j]: j = (((mt*16+ks)*32+lane)*8+aidx)
        int j = tid;
        int aidx = j & 7, lane = (j >> 3) & 31, ks = (j >> 8) & 15, mt = j >> 12;
        int m = (lane >> 2) | (((aidx >> 1) & 1) << 3);
        int k = ((lane & 3) << 1) | (aidx & 1) | ((aidx >> 2) << 3);
        g_WpH[j] = __float2half(pjw[(((mt << 4) + m) << 8) + (ks << 4) + k]);
    } else {
        int u = tid - 65536;   // 0..8191 -> float4 of g_BiasC
        int h = u >> 10, mt = (u >> 8) & 3, nt = (u >> 5) & 7, lane = u & 31;
        int g = lane >> 2, t = lane & 3;
        int n0 = mt * 16 + g, m0 = nt * 8 + t * 2;
        float4 v;
        v.x = atb[(h << 6) + bix[(n0 << 6) + m0]];
        v.y = atb[(h << 6) + bix[(n0 << 6) + m0 + 1]];
        v.z = atb[(h << 6) + bix[((n0 + 8) << 6) + m0]];
        v.w = atb[(h << 6) + bix[((n0 + 8) << 6) + m0 + 1]];
        ((float4*)g_BiasC)[u] = v;
    }
}

__device__ __forceinline__ void hmma16816(float* c4, const uint32_t* a4,
                                          uint32_t b0, uint32_t b1) {
    asm volatile(
        "mma.sync.aligned.m16n8k16.row.col.f32.f16.f16.f32 "
        "{%0,%1,%2,%3}, {%4,%5,%6,%7}, {%8,%9}, {%0,%1,%2,%3};"
        : "+f"(c4[0]), "+f"(c4[1]), "+f"(c4[2]), "+f"(c4[3])
        : "r"(a4[0]), "r"(a4[1]), "r"(a4[2]), "r"(a4[3]), "r"(b0), "r"(b1));
}

__device__ __forceinline__ void barn(int id, int cnt) {
    asm volatile("bar.sync %0, %1;" :: "r"(id), "r"(cnt) : "memory");
}

// ---- shared memory layout (bytes) ----
// @0      LL16 f16 [256][64] (32768) | PO_LO f32 [128][64] (phase C/D)
// @32768  S_lh f16 [256][64] (32768)
// @65536  hlT  f16 [64][266] (34048)
// @99584  S_hh f16 [256][64] (32768)
// @132352 P f16 [4][64][72] (36864) | S_wt(A) | PO_HI f32 [128][64]
// @169216 Q f16 [64][134]   (17152) | IW f32[4096] (loaded during B(b1))
// @186368 actT f16 [64][264] (33792)
// @220160 V16A f16 [32][72] (4608)
// @224768 V16B f16 [32][72] (4608)  -> end 229376
#define SMEM_BYTES 229376

__global__ void __launch_bounds__(NTH, 1)
wwa_kernel(const float* __restrict__ x,   const float* __restrict__ wtf,
           const float* __restrict__ iwtf,const float* __restrict__ dww,
           const float* __restrict__ dwb, const float* __restrict__ pjb,
           float* __restrict__ out)
{
    extern __shared__ unsigned char sm[];
    __half* LL16 = (__half*)sm;
    __half* S_lh = (__half*)(sm + 32768);
    __half* hlT  = (__half*)(sm + 65536);
    __half* S_hh = (__half*)(sm + 99584);
    __half* P    = (__half*)(sm + 132352);
    float*  S_wt = (float*)(sm + 132352);
    float*  PO_LO = (float*)sm;                 // proj rows 0..127
    float*  PO_HI = (float*)(sm + 132352);      // proj rows 128..255
    __half* Q    = (__half*)(sm + 169216);
    float*  IW   = (float*)(sm + 169216);       // iwtf, loaded during B(b1)
    __half* actT = (__half*)(sm + 186368);
    __half* V16A = (__half*)(sm + 220160);
    __half* V16B = (__half*)(sm + 224768);

    const int tid  = threadIdx.x;
    const int wid  = tid >> 5;
    const int lane = tid & 31;
    const int widx = blockIdx.x;
    const int wb = widx >> 8;
    const int wy = (widx >> 4) & 15;
    const int wx = widx & 15;

    // ---- init: wavelet filters ----
    for (int i = tid; i < 4096; i += NTH) S_wt[i] = wtf[i];
    __syncthreads();

    // ================= Phase A: forward wavelet =================
    {
        const float* xb = x + (size_t)wb * (256u * 256u * 256u);
        #pragma unroll 4
        for (int rep = 0; rep < 8; rep++) {
            int u = tid + rep * NTH;        // (c, i, k)
            int c = u >> 5;
            int i = (u >> 2) & 7;
            int k = u & 3;
            int gy = (wy << 4) + (i << 1);
            int gx = (wx << 4) + (k << 2);
            const float* p = xb + (((c << 8) + gy) << 8) + gx;
            float4 a = *(const float4*)p;
            float4 b = *(const float4*)(p + 256);
            const float* w = S_wt + (c << 4);
            int pix = (i << 3) + (k << 1);
            int o0 = (c << 6) + pix;
            float v0, v1;
            v0 = a.x*w[0] + a.y*w[1] + b.x*w[2] + b.y*w[3];
            v1 = a.z*w[0] + a.w*w[1] + b.z*w[2] + b.w*w[3];
            *(__half2*)(LL16 + o0) = __floats2half2_rn(v0, v1);
            v0 = a.x*w[4] + a.y*w[5] + b.x*w[6] + b.y*w[7];
            v1 = a.z*w[4] + a.w*w[5] + b.z*w[6] + b.w*w[7];
            *(__half2*)(S_lh + o0) = __floats2half2_rn(v0, v1);
            v0 = a.x*w[8] + a.y*w[9] + b.x*w[10] + b.y*w[11];
            v1 = a.z*w[8] + a.w*w[9] + b.z*w[10] + b.w*w[11];
            hlT[pix * HTS + c]       = __float2half(v0);
            hlT[(pix + 1) * HTS + c] = __float2half(v1);
            v0 = a.x*w[12] + a.y*w[13] + b.x*w[14] + b.y*w[15];
            v1 = a.z*w[12] + a.w*w[13] + b.z*w[14] + b.w*w[15];
            *(__half2*)(S_hh + o0) = __floats2half2_rn(v0, v1);
        }
    }
    __syncthreads();

    // head-0 v init: V16A[d][m] = LL16[d][m]
    {
        int d  = tid >> 5;
        int m2 = (tid & 31) << 1;
        *(__half2*)(V16A + d * VSTR + m2) = *(const __half2*)(LL16 + (d << 6) + m2);
    }

    // ---- B1a(batch0): q-conv channels 0..127, all 32 warps ----
    #pragma unroll
    for (int rep = 0; rep < 4; rep++) {
        int e  = tid + rep * NTH;      // 4096 strips
        int cl = e >> 5;               // warp-uniform
        int s  = e & 31;
        int py = s >> 2;
        int px0 = (s & 3) << 1;
        int base = px0 >> 1;
        const float* wd = dww + cl * 25;
        float a0 = __ldg(dwb + cl), a1 = a0;
        const __half2* row = (const __half2*)(S_lh + (cl << 6));
        #pragma unroll
        for (int uu = 0; uu < 5; uu++) {
            int yy = py + uu - 2;
            if ((unsigned)yy < 8u) {
                const __half2* r = row + (yy << 2);
                const float* w = wd + uu * 5;
                if (base >= 1) {
                    float2 h = __half22float2(r[base - 1]);
                    a0 += h.x * w[0] + h.y * w[1];
                    a1 += h.y * w[0];
                }
                {
                    float2 h = __half22float2(r[base]);
                    a0 += h.x * w[2] + h.y * w[3];
                    a1 += h.x * w[1] + h.y * w[2];
                }
                if (base <= 2) {
                    float2 h = __half22float2(r[base + 1]);
                    a0 += h.x * w[4];
                    a1 += h.x * w[3] + h.y * w[4];
                }
            }
        }
        int n = (py << 3) + px0;
        Q[n * QS + cl]       = __float2half(a0 * SCQ);
        Q[(n + 1) * QS + cl] = __float2half(a1 * SCQ);
    }
    __syncthreads();

    // ================= Phase B: 2 batches, warp-specialized =================
    for (int bb = 0; bb < 2; bb++) {
        if (wid < 16) {
            // ---- B1b(bb): QK^T via HMMA, raw bias C-init, reg softmax -> P ----
            const int hl = wid >> 2;
            const int mt = wid & 3;
            const int g  = lane >> 2;
            const int t  = lane & 3;
            const int chb = hl << 5;
            float fv0[16], fv1[16];
            {
                const float4* bc = (const float4*)g_BiasC
                    + ((((bb << 2) + hl) * 4 + mt) << 8) + lane;
                #pragma unroll
                for (int nt = 0; nt < 8; nt++) {
                    float4 b4 = bc[nt << 5];
                    fv0[nt*2] = b4.x; fv0[nt*2+1] = b4.y;
                    fv1[nt*2] = b4.z; fv1[nt*2+1] = b4.w;
                }
            }
            const __half* qb = Q + (mt * 16 + g) * QS + chb + (t << 1);
            uint32_t A0[4], A1[4];
            A0[0] = *(const uint32_t*)(qb);
            A0[1] = *(const uint32_t*)(qb + 8 * QS);
            A0[2] = *(const uint32_t*)(qb + 8);
            A0[3] = *(const uint32_t*)(qb + 8 * QS + 8);
            A1[0] = *(const uint32_t*)(qb + 16);
            A1[1] = *(const uint32_t*)(qb + 8 * QS + 16);
            A1[2] = *(const uint32_t*)(qb + 24);
            A1[3] = *(const uint32_t*)(qb + 8 * QS + 24);
            barn(4, 1024);                 // Q reads done -> other half may reuse Q
            const __half* bt = hlT + (bb << 7) + chb + (t << 1);
            #pragma unroll
            for (int nt = 0; nt < 8; nt++) {
                float c[4] = {fv0[nt*2], fv0[nt*2+1], fv1[nt*2], fv1[nt*2+1]};
                const __half* bp = bt + ((nt << 3) + g) * HTS;
                uint32_t b0 = *(const uint32_t*)(bp);
                uint32_t b1 = *(const uint32_t*)(bp + 8);
                hmma16816(c, A0, b0, b1);
                b0 = *(const uint32_t*)(bp + 16);
                b1 = *(const uint32_t*)(bp + 24);
                hmma16816(c, A1, b0, b1);
                fv0[nt*2] = c[0]; fv0[nt*2+1] = c[1];
                fv1[nt*2] = c[2]; fv1[nt*2+1] = c[3];
            }
            #pragma unroll
            for (int r = 0; r < 2; r++) {
                float* fv = r ? fv1 : fv0;
                int n = mt * 16 + g + (r << 3);
                float mx = fv[0];
                #pragma unroll
                for (int j = 1; j < 16; j++) mx = fmaxf(mx, fv[j]);
                mx = fmaxf(mx, __shfl_xor_sync(0xffffffffu, mx, 1));
                mx = fmaxf(mx, __shfl_xor_sync(0xffffffffu, mx, 2));
                float sum = 0.f;
                #pragma unroll
                for (int j = 0; j < 16; j++) { fv[j] = __expf(fv[j] - mx); sum += fv[j]; }
                sum += __shfl_xor_sync(0xffffffffu, sum, 1);
                sum += __shfl_xor_sync(0xffffffffu, sum, 2);
                float inv = 1.f / sum;
                __half* pr = P + hl * PHEAD + n * PSTR + (t << 1);
                #pragma unroll
                for (int nt = 0; nt < 8; nt++)
                    *(__half2*)(pr + (nt << 3)) =
                        __floats2half2_rn(fv[nt*2] * inv, fv[nt*2+1] * inv);
            }
            barn(3, 512);                  // P visible to all PV warps

            // ---- B2(bb): 4 chained heads, PV via HMMA, V16 double-buffered ----
            const int mt2 = wid >> 3;
            const int nt2 = wid & 7;
            for (int hl2 = 0; hl2 < 4; hl2++) {
                const int hd  = (bb << 2) + hl2;
                const int ch0 = hd << 5;
                __half* Vcur = (hd & 1) ? V16B : V16A;
                __half* Vnxt = (hd & 1) ? V16A : V16B;
                float c[4] = {0.f, 0.f, 0.f, 0.f};
                const __half* ab2 = Vcur + (mt2 * 16 + g) * VSTR + (t << 1);
                const __half* bb2 = P + hl2 * PHEAD + ((nt2 << 3) + g) * PSTR + (t << 1);
                #pragma unroll
                for (int ks = 0; ks < 4; ks++) {
                    uint32_t a4[4], b0, b1;
                    a4[0] = *(const uint32_t*)(ab2 + (ks << 4));
                    a4[1] = *(const uint32_t*)(ab2 + 8 * VSTR + (ks << 4));
                    a4[2] = *(const uint32_t*)(ab2 + (ks << 4) + 8);
                    a4[3] = *(const uint32_t*)(ab2 + 8 * VSTR + (ks << 4) + 8);
                    b0 = *(const uint32_t*)(bb2 + (ks << 4));
                    b1 = *(const uint32_t*)(bb2 + (ks << 4) + 8);
                    hmma16816(c, a4, b0, b1);
                }
                int d0 = mt2 * 16 + g;
                int n0 = (nt2 << 3) + (t << 1);
                actT[n0 * 264 + ch0 + d0]           = __float2half(fmaxf(c[0], 0.f));
                actT[(n0 + 1) * 264 + ch0 + d0]     = __float2half(fmaxf(c[1], 0.f));
                actT[n0 * 264 + ch0 + d0 + 8]       = __float2half(fmaxf(c[2], 0.f));
                actT[(n0 + 1) * 264 + ch0 + d0 + 8] = __float2half(fmaxf(c[3], 0.f));
                if (hd < 7) {
                    float2 f0 = __half22float2(*(const __half2*)(LL16 + ((ch0 + 32 + d0) << 6) + n0));
                    float2 f1 = __half22float2(*(const __half2*)(LL16 + ((ch0 + 40 + d0) << 6) + n0));
                    *(__half2*)(Vnxt + d0 * VSTR + n0)       = __floats2half2_rn(c[0] + f0.x, c[1] + f0.y);
                    *(__half2*)(Vnxt + (d0 + 8) * VSTR + n0) = __floats2half2_rn(c[2] + f1.x, c[3] + f1.y);
                }
                barn(5 + mt2, 256);        // Vnxt writes visible within group
            }
        } else {
            barn(4, 1024);                 // wait for B1b(bb)'s Q reads
            if (bb == 0) {
                // ---- B1a(batch1): q-conv channels 128..255, warps 16-31 ----
                #pragma unroll
                for (int rep = 0; rep < 8; rep++) {
                    int e  = (tid - 512) + rep * 512;   // 4096 strips
                    int cl = e >> 5;                    // warp-uniform
                    int s  = e & 31;
                    int py = s >> 2;
                    int px0 = (s & 3) << 1;
                    int base = px0 >> 1;
                    const float* wd = dww + 3200 + cl * 25;
                    float a0 = __ldg(dwb + 128 + cl), a1 = a0;
                    const __half2* row = (const __half2*)(S_lh + ((128 + cl) << 6));
                    #pragma unroll
                    for (int uu = 0; uu < 5; uu++) {
                        int yy = py + uu - 2;
                        if ((unsigned)yy < 8u) {
                            const __half2* r = row + (yy << 2);
                            const float* w = wd + uu * 5;
                            if (base >= 1) {
                                float2 h = __half22float2(r[base - 1]);
                                a0 += h.x * w[0] + h.y * w[1];
                                a1 += h.y * w[0];
                            }
                            {
                                float2 h = __half22float2(r[base]);
                                a0 += h.x * w[2] + h.y * w[3];
                                a1 += h.x * w[1] + h.y * w[2];
                            }
                            if (base <= 2) {
                                float2 h = __half22float2(r[base + 1]);
                                a0 += h.x * w[4];
                                a1 += h.x * w[3] + h.y * w[4];
                            }
                        }
                    }
                    int n = (py << 3) + px0;
                    Q[n * QS + cl]       = __float2half(a0 * SCQ);
                    Q[(n + 1) * QS + cl] = __float2half(a1 * SCQ);
                }
            } else {
                // ---- prefetch iwtf into dead Q region ----
                #pragma unroll
                for (int rep = 0; rep < 8; rep++)
                    IW[(tid - 512) + rep * 512] = iwtf[(tid - 512) + rep * 512];
            }
        }
        __syncthreads();
    }

    // ===== Phase C: HMMA projection (actT built by B2) =====
    {
        const int mt = wid >> 1;
        const int nh = wid & 1;
        const int g  = lane >> 2;
        const int t  = lane & 3;
        float acc[4][4];
        #pragma unroll
        for (int i = 0; i < 4; i++)
            #pragma unroll
            for (int j = 0; j < 4; j++) acc[i][j] = 0.f;

        const uint4* afrag = (const uint4*)g_WpH + (mt << 9) + lane;
        const __half* bbase = actT + ((nh << 5) + g) * 264 + (t << 1);
        #pragma unroll 4
        for (int ks = 0; ks < 16; ks++) {
            uint4 a = afrag[ks << 5];
            const __half* bp = bbase + (ks << 4);
            #pragma unroll
            for (int ntl = 0; ntl < 4; ntl++) {
                uint32_t b0 = *(const uint32_t*)(bp + ntl * 8 * 264);
                uint32_t b1 = *(const uint32_t*)(bp + ntl * 8 * 264 + 8);
                hmma16816(acc[ntl], (const uint32_t*)&a, b0, b1);
            }
        }
        // epilogue: bias + store to split proj_out (disjoint from actT reads)
        int o0 = (mt << 4) + g;
        float pb0 = pjb[o0], pb1 = pjb[o0 + 8];
        float* d0 = (o0 < 128) ? (PO_LO + (o0 << 6)) : (PO_HI + ((o0 - 128) << 6));
        float* d1 = (o0 < 128) ? (PO_LO + ((o0 + 8) << 6)) : (PO_HI + ((o0 - 120) << 6));
        int ncol = (nh << 5) + (t << 1);
        #pragma unroll
        for (int ntl = 0; ntl < 4; ntl++) {
            int nc = ncol + (ntl << 3);
            *(float2*)(d0 + nc) = make_float2(acc[ntl][0] + pb0, acc[ntl][1] + pb0);
            *(float2*)(d1 + nc) = make_float2(acc[ntl][2] + pb1, acc[ntl][3] + pb1);
        }
    }
    __syncthreads();

    // ================= Phase D: inverse wavelet -> out =================
    {
        float* ob = out + (size_t)wb * (256u * 256u * 256u);
        #pragma unroll 4
        for (int rep = 0; rep < 8; rep++) {
            int u = tid + rep * NTH;
            int c = u >> 5;
            int i = (u >> 2) & 7;
            int k = u & 3;
            int pix = (i << 3) + (k << 1);
            int o0 = (c << 6) + pix;
            const float* w = IW + (c << 4);
            const float* llrow = (c < 128) ? (PO_LO + (c << 6)) : (PO_HI + ((c - 128) << 6));
            float2 llv = *(const float2*)(llrow + pix);
            float2 lh = __half22float2(*(const __half2*)(S_lh + o0));
            float2 hl;
            hl.x = __half2float(hlT[pix * HTS + c]);
            hl.y = __half2float(hlT[(pix + 1) * HTS + c]);
            float2 hh = __half22float2(*(const __half2*)(S_hh + o0));
            float4 r0, r1;
            r0.x = llv.x*w[0] + lh.x*w[4] + hl.x*w[8]  + hh.x*w[12];
            r0.y = llv.x*w[1] + lh.x*w[5] + hl.x*w[9]  + hh.x*w[13];
            r0.z = llv.y*w[0] + lh.y*w[4] + hl.y*w[8]  + hh.y*w[12];
            r0.w = llv.y*w[1] + lh.y*w[5] + hl.y*w[9]  + hh.y*w[13];
            r1.x = llv.x*w[2] + lh.x*w[6] + hl.x*w[10] + hh.x*w[14];
            r1.y = llv.x*w[3] + lh.x*w[7] + hl.x*w[11] + hh.x*w[15];
            r1.z = llv.y*w[2] + lh.y*w[6] + hl.y*w[10] + hh.y*w[14];
            r1.w = llv.y*w[3] + lh.y*w[7] + hl.y*w[11] + hh.y*w[15];
            int gy = (wy << 4) + (i << 1);
            int gx = (wx << 4) + (k << 2);
            float* q_ = ob + (((c << 8) + gy) << 8) + gx;
            *(float4*)q_ = r0;
            *(float4*)(q_ + 256) = r1;
        }
    }
}

extern "C" void kernel_launch(void* const* d_in, const int* in_sizes, int n_in,
                              void* d_out, int out_size) {
    const float* x    = (const float*)d_in[0];
    const float* wtf  = (const float*)d_in[1];
    const float* iwtf = (const float*)d_in[2];
    const float* dww  = (const float*)d_in[3];
    const float* dwb  = (const float*)d_in[4];
    const float* pjw  = (const float*)d_in[5];
    const float* pjb  = (const float*)d_in[6];
    const float* atb  = (const float*)d_in[7];
    const int*   bix  = (const int*)d_in[8];
    float* o = (float*)d_out;
    (void)in_sizes; (void)n_in; (void)out_size;
    prep_all<<<288, 256>>>(pjw, atb, bix);
    cudaFuncSetAttribute(wwa_kernel, cudaFuncAttributeMaxDynamicSharedMemorySize, SMEM_BYTES);
    wwa_kernel<<<512, NTH, SMEM_BYTES>>>(x, wtf, iwtf, dww, dwb, pjb, o);
}